// round 3
// baseline (speedup 1.0000x reference)
#include <cuda_runtime.h>

// Fixed problem sizes
#define NN 100000
#define EE 1600000
#define DD 128
#define NG 64

// ---------------- scratch (static device globals; no allocation) ----------------
__device__ int   g_ei64, g_b64;
__device__ float g_deg[NN];
__device__ float g_winv[NN];             // 1/max(deg,1)
__device__ float g_wdst[NN];             // winv[n] / max(cnt[batch[n]],1)
__device__ float g_cnt[NG];
__device__ float g_agg[(size_t)NN * DD];
__device__ float g_h1[(size_t)NN * DD];
__device__ float g_h2[(size_t)NN * DD];
__device__ float g_z[(size_t)NN * 4];    // per node: [zl0, zl1, zr0, zr1]
__device__ float g_Wcl[DD * 2];          // Wl3 @ Wlin
__device__ float g_Wcr[DD * 2];          // Wr3 @ Wlin
__device__ float g_cb[2];                // bl3 @ Wlin + blin
__device__ float g_acc[NG * 2];          // output accumulator

// ---------------- dtype detection (int32 vs int64), robust ----------------
__global__ void detect_kernel(const void* ei, const void* batch) {
    const long long* p = (const long long*)ei;
    bool e64 = true;
    #pragma unroll
    for (int i = 0; i < 16; i++) {
        long long v = p[(size_t)i * 99991];
        if (v < 0 || v >= NN) e64 = false;
    }
    g_ei64 = e64 ? 1 : 0;
    // batch is sorted; sample near the end (first half of int64 slots is safe
    // for both dtypes; under int32 truth the high word there is ~63 != 0).
    const long long* q = (const long long*)batch;
    bool b64 = true;
    #pragma unroll
    for (int i = 0; i < 8; i++) {
        long long v = q[NN / 2 - 1 - i * 37];
        if (v < 0 || v >= NG) b64 = false;
    }
    g_b64 = b64 ? 1 : 0;
}

__device__ __forceinline__ int ld_ei(const void* p, long long i) {
    return g_ei64 ? (int)((const long long*)p)[i] : ((const int*)p)[i];
}
__device__ __forceinline__ int ld_b(const void* p, long long i) {
    return g_b64 ? (int)((const long long*)p)[i] : ((const int*)p)[i];
}

// ---------------- zeroing ----------------
__global__ void zero_small_kernel() {
    int i = blockIdx.x * blockDim.x + threadIdx.x;
    if (i < NN) g_deg[i] = 0.0f;
    if (i < NG) g_cnt[i] = 0.0f;
    if (i < NG * 2) g_acc[i] = 0.0f;
}

__global__ void zero_agg_kernel() {
    long long i = (long long)blockIdx.x * blockDim.x + threadIdx.x;
    const long long n4 = (long long)NN * DD / 4;
    if (i < n4) ((float4*)g_agg)[i] = make_float4(0.f, 0.f, 0.f, 0.f);
}

// ---------------- degree / counts / weights ----------------
__global__ void deg_kernel(const void* __restrict__ ei) {
    int e = blockIdx.x * blockDim.x + threadIdx.x;
    if (e >= EE) return;
    unsigned d = (unsigned)ld_ei(ei, (long long)EE + e);
    if (d >= NN) return;
    atomicAdd(&g_deg[d], 1.0f);
}

__global__ void cnt_kernel(const void* __restrict__ batch) {
    int i = blockIdx.x * blockDim.x + threadIdx.x;
    if (i >= NN) return;
    unsigned g = (unsigned)ld_b(batch, i);
    if (g >= NG) return;
    atomicAdd(&g_cnt[g], 1.0f);
}

__global__ void prep_kernel(const void* __restrict__ batch) {
    int i = blockIdx.x * blockDim.x + threadIdx.x;
    if (i >= NN) return;
    float w = 1.0f / fmaxf(g_deg[i], 1.0f);
    g_winv[i] = w;
    unsigned g = (unsigned)ld_b(batch, i);
    float c = (g < NG) ? g_cnt[g] : 1.0f;
    g_wdst[i] = w / fmaxf(c, 1.0f);
}

// ---------------- edge scatter: g_agg[dst] += X[src] (128 floats, warp/edge) ----------------
__global__ void __launch_bounds__(256) scatter_kernel(const float* __restrict__ X,
                                                      const void* __restrict__ ei) {
    long long idx = (long long)blockIdx.x * blockDim.x + threadIdx.x;
    int e = (int)(idx >> 5);
    int lane = (int)(idx & 31);
    if (e >= EE) return;
    unsigned s = (unsigned)ld_ei(ei, e);
    unsigned d = (unsigned)ld_ei(ei, (long long)EE + e);
    if (s >= NN || d >= NN) return;
    float4 v = ((const float4*)(X + (size_t)s * DD))[lane];
    unsigned long long ap =
        (unsigned long long)__cvta_generic_to_global(g_agg + (size_t)d * DD + lane * 4);
    asm volatile("red.global.add.v4.f32 [%0], {%1,%2,%3,%4};"
                 :: "l"(ap), "f"(v.x), "f"(v.y), "f"(v.z), "f"(v.w) : "memory");
}

// ---------------- fused layer GEMM: H = relu(agg*winv @ Wl + X @ Wr + b) ----------------
// Tile: 64 rows x 128 cols, 256 threads, 8x4 register micro-tile, BK=16.
__global__ void __launch_bounds__(256) gemm_relu_kernel(const float* __restrict__ X,
                                                        const float* __restrict__ Wl,
                                                        const float* __restrict__ Wr,
                                                        const float* __restrict__ bias,
                                                        float* __restrict__ H) {
    __shared__ __align__(16) float As[16][64];
    __shared__ __align__(16) float Ws[16][128];

    int t = threadIdx.x;
    int ty = t >> 5;
    int tx = t & 31;
    int row0 = blockIdx.x * 64;

    float c[8][4];
    #pragma unroll
    for (int i = 0; i < 8; i++)
        #pragma unroll
        for (int j = 0; j < 4; j++) c[i][j] = 0.0f;

    int lrow = t >> 2;
    int lk4 = (t & 3) * 4;
    int wk = t >> 4;
    int wj = (t & 15) * 8;

    #pragma unroll
    for (int phase = 0; phase < 2; phase++) {
        const float* A = phase ? X : g_agg;
        const float* W = phase ? Wr : Wl;
        for (int ko = 0; ko < DD; ko += 16) {
            int arow = row0 + lrow;
            float4 av = make_float4(0.f, 0.f, 0.f, 0.f);
            if (arow < NN) {
                av = *(const float4*)(A + (size_t)arow * DD + ko + lk4);
                if (phase == 0) {
                    float sc = g_winv[arow];
                    av.x *= sc; av.y *= sc; av.z *= sc; av.w *= sc;
                }
            }
            float4 w0 = *(const float4*)(W + (size_t)(ko + wk) * DD + wj);
            float4 w1 = *(const float4*)(W + (size_t)(ko + wk) * DD + wj + 4);

            __syncthreads();
            As[lk4 + 0][lrow] = av.x;
            As[lk4 + 1][lrow] = av.y;
            As[lk4 + 2][lrow] = av.z;
            As[lk4 + 3][lrow] = av.w;
            *(float4*)&Ws[wk][wj] = w0;
            *(float4*)&Ws[wk][wj + 4] = w1;
            __syncthreads();

            #pragma unroll
            for (int k = 0; k < 16; k++) {
                float4 a0 = *(const float4*)&As[k][ty * 8];
                float4 a1 = *(const float4*)&As[k][ty * 8 + 4];
                float4 w = *(const float4*)&Ws[k][tx * 4];
                float avv[8] = {a0.x, a0.y, a0.z, a0.w, a1.x, a1.y, a1.z, a1.w};
                float wvv[4] = {w.x, w.y, w.z, w.w};
                #pragma unroll
                for (int i = 0; i < 8; i++)
                    #pragma unroll
                    for (int j = 0; j < 4; j++)
                        c[i][j] += avv[i] * wvv[j];
            }
        }
    }

    float4 b = *(const float4*)(bias + tx * 4);
    #pragma unroll
    for (int i = 0; i < 8; i++) {
        int r = row0 + ty * 8 + i;
        if (r < NN) {
            float4 o;
            o.x = fmaxf(c[i][0] + b.x, 0.0f);
            o.y = fmaxf(c[i][1] + b.y, 0.0f);
            o.z = fmaxf(c[i][2] + b.z, 0.0f);
            o.w = fmaxf(c[i][3] + b.w, 0.0f);
            *(float4*)(H + (size_t)r * DD + tx * 4) = o;
        }
    }
}

// ---------------- layer-3 fold: Wcl=Wl3@Wlin, Wcr=Wr3@Wlin, cb=bl3@Wlin+blin ----------------
__global__ void foldW_kernel(const float* __restrict__ Wl3, const float* __restrict__ Wr3,
                             const float* __restrict__ bl3, const float* __restrict__ Wlin,
                             const float* __restrict__ blin) {
    int k = threadIdx.x;  // 0..127
    float a0 = 0.f, a1 = 0.f, b0 = 0.f, b1 = 0.f;
    for (int m = 0; m < DD; m++) {
        float wl = Wl3[k * DD + m], wr = Wr3[k * DD + m];
        float l0 = Wlin[m * 2 + 0], l1 = Wlin[m * 2 + 1];
        a0 += wl * l0; a1 += wl * l1;
        b0 += wr * l0; b1 += wr * l1;
    }
    g_Wcl[k * 2 + 0] = a0; g_Wcl[k * 2 + 1] = a1;
    g_Wcr[k * 2 + 0] = b0; g_Wcr[k * 2 + 1] = b1;
    if (k < 2) {
        float cv = blin[k];
        for (int m = 0; m < DD; m++) cv += bl3[m] * Wlin[m * 2 + k];
        g_cb[k] = cv;
    }
}

// ---------------- project h2 -> 4 scalars per node ----------------
__global__ void __launch_bounds__(256) proj3_kernel() {
    long long idx = (long long)blockIdx.x * blockDim.x + threadIdx.x;
    int node = (int)(idx >> 5);
    int lane = (int)(idx & 31);
    if (node >= NN) return;  // warp-per-node: whole warp exits together
    float4 h = ((const float4*)(g_h2 + (size_t)node * DD))[lane];
    float hv[4] = {h.x, h.y, h.z, h.w};
    float s0 = 0.f, s1 = 0.f, s2 = 0.f, s3 = 0.f;
    #pragma unroll
    for (int j = 0; j < 4; j++) {
        int k = lane * 4 + j;
        s0 += hv[j] * g_Wcl[k * 2 + 0];
        s1 += hv[j] * g_Wcl[k * 2 + 1];
        s2 += hv[j] * g_Wcr[k * 2 + 0];
        s3 += hv[j] * g_Wcr[k * 2 + 1];
    }
    #pragma unroll
    for (int o = 16; o > 0; o >>= 1) {
        s0 += __shfl_down_sync(0xFFFFFFFFu, s0, o);
        s1 += __shfl_down_sync(0xFFFFFFFFu, s1, o);
        s2 += __shfl_down_sync(0xFFFFFFFFu, s2, o);
        s3 += __shfl_down_sync(0xFFFFFFFFu, s3, o);
    }
    if (lane == 0) ((float4*)g_z)[node] = make_float4(s0, s1, s2, s3);
}

// ---------------- layer-3 pooled reductions ----------------
__global__ void __launch_bounds__(256) edge3_kernel(const void* __restrict__ ei,
                                                    const void* __restrict__ batch) {
    __shared__ float s[NG * 2];
    for (int i = threadIdx.x; i < NG * 2; i += blockDim.x) s[i] = 0.0f;
    __syncthreads();
    for (long long e = (long long)blockIdx.x * blockDim.x + threadIdx.x; e < EE;
         e += (long long)gridDim.x * blockDim.x) {
        unsigned sr = (unsigned)ld_ei(ei, e);
        unsigned d = (unsigned)ld_ei(ei, (long long)EE + e);
        if (sr >= NN || d >= NN) continue;
        unsigned g = (unsigned)ld_b(batch, d);
        if (g >= NG) continue;
        float w = g_wdst[d];
        float2 zl = *(const float2*)(g_z + (size_t)sr * 4);
        atomicAdd(&s[g * 2 + 0], w * zl.x);
        atomicAdd(&s[g * 2 + 1], w * zl.y);
    }
    __syncthreads();
    for (int i = threadIdx.x; i < NG * 2; i += blockDim.x) atomicAdd(&g_acc[i], s[i]);
}

__global__ void __launch_bounds__(256) node3_kernel(const void* __restrict__ batch) {
    __shared__ float s[NG * 2];
    for (int i = threadIdx.x; i < NG * 2; i += blockDim.x) s[i] = 0.0f;
    __syncthreads();
    for (long long nd = (long long)blockIdx.x * blockDim.x + threadIdx.x; nd < NN;
         nd += (long long)gridDim.x * blockDim.x) {
        unsigned g = (unsigned)ld_b(batch, nd);
        if (g >= NG) continue;
        float ci = 1.0f / fmaxf(g_cnt[g], 1.0f);
        float2 zr = *(const float2*)(g_z + (size_t)nd * 4 + 2);
        atomicAdd(&s[g * 2 + 0], ci * zr.x);
        atomicAdd(&s[g * 2 + 1], ci * zr.y);
    }
    __syncthreads();
    for (int i = threadIdx.x; i < NG * 2; i += blockDim.x) atomicAdd(&g_acc[i], s[i]);
}

__global__ void finalize_kernel(float* __restrict__ out) {
    int t = threadIdx.x;
    if (t < NG * 2) out[t] = g_acc[t] + g_cb[t & 1];
}

// ---------------- host launcher ----------------
extern "C" void kernel_launch(void* const* d_in, const int* in_sizes, int n_in,
                              void* d_out, int out_size) {
    // Default: reference dict order
    int iX = 0, iEI = 1, iB = 2;
    int iWl1 = 3, ibl1 = 4, iWr1 = 5;
    int iWl2 = 6, ibl2 = 7, iWr2 = 8;
    int iWl3 = 9, ibl3 = 10, iWr3 = 11;
    int iWlin = 12, iblin = 13;

    if (n_in >= 14) {
        bool dict_ok = (in_sizes[0] == NN * DD) && (in_sizes[2] == NN) &&
                       (in_sizes[12] == DD * 2) && (in_sizes[13] == 2);
        if (!dict_ok && in_sizes[13] == NN * DD) {
            // alphabetical: Wl1,Wl2,Wl3,Wlin,Wr1,Wr2,Wr3,batch,bl1,bl2,bl3,blin,edge_index,x
            iWl1 = 0; iWl2 = 1; iWl3 = 2; iWlin = 3;
            iWr1 = 4; iWr2 = 5; iWr3 = 6; iB = 7;
            ibl1 = 8; ibl2 = 9; ibl3 = 10; iblin = 11;
            iEI = 12; iX = 13;
        }
    }

    const float* x = (const float*)d_in[iX];
    const void* ei = d_in[iEI];
    const void* batch = d_in[iB];
    const float* Wl1 = (const float*)d_in[iWl1];
    const float* bl1 = (const float*)d_in[ibl1];
    const float* Wr1 = (const float*)d_in[iWr1];
    const float* Wl2 = (const float*)d_in[iWl2];
    const float* bl2 = (const float*)d_in[ibl2];
    const float* Wr2 = (const float*)d_in[iWr2];
    const float* Wl3 = (const float*)d_in[iWl3];
    const float* bl3 = (const float*)d_in[ibl3];
    const float* Wr3 = (const float*)d_in[iWr3];
    const float* Wlin = (const float*)d_in[iWlin];
    const float* blin = (const float*)d_in[iblin];
    float* out = (float*)d_out;

    // CRITICAL: __device__ symbols are NOT valid host-side pointers; resolve
    // real device addresses before passing them as kernel arguments.
    float *h1p = nullptr, *h2p = nullptr;
    cudaGetSymbolAddress((void**)&h1p, g_h1);
    cudaGetSymbolAddress((void**)&h2p, g_h2);

    detect_kernel<<<1, 1>>>(ei, batch);

    zero_small_kernel<<<(NN + 255) / 256, 256>>>();
    deg_kernel<<<(EE + 255) / 256, 256>>>(ei);
    cnt_kernel<<<(NN + 255) / 256, 256>>>(batch);
    prep_kernel<<<(NN + 255) / 256, 256>>>(batch);

    const int gemm_blocks = (NN + 63) / 64;
    const int agg_blocks = (int)(((long long)NN * DD / 4 + 255) / 256);
    const int scat_blocks = (int)(((long long)EE * 32 + 255) / 256);

    // layer 1
    zero_agg_kernel<<<agg_blocks, 256>>>();
    scatter_kernel<<<scat_blocks, 256>>>(x, ei);
    gemm_relu_kernel<<<gemm_blocks, 256>>>(x, Wl1, Wr1, bl1, h1p);

    // layer 2
    zero_agg_kernel<<<agg_blocks, 256>>>();
    scatter_kernel<<<scat_blocks, 256>>>(h1p, ei);
    gemm_relu_kernel<<<gemm_blocks, 256>>>(h1p, Wl2, Wr2, bl2, h2p);

    // layer 3 folded through the linear head (no relu before pooling)
    foldW_kernel<<<1, 128>>>(Wl3, Wr3, bl3, Wlin, blin);
    proj3_kernel<<<(int)(((long long)NN * 32 + 255) / 256), 256>>>();
    edge3_kernel<<<1024, 256>>>(ei, batch);
    node3_kernel<<<256, 256>>>(batch);
    finalize_kernel<<<1, 128>>>(out);
}

// round 4
// speedup vs baseline: 1.8234x; 1.8234x over previous
#include <cuda_runtime.h>
#include <cstdint>

#define NN 100000
#define EE 1600000
#define DD 128
#define NG 64

// ---------------- scratch (static device globals; no allocation) ----------------
__device__ int   g_ei64, g_b64;
__device__ int   g_degi[NN];
__device__ int   g_start[NN];
__device__ int   g_cursor[NN];
__device__ int   g_bsum[512];
__device__ int   g_cnti[NG];
__device__ int   g_csr[EE];
__device__ float g_winv[NN];
__device__ float g_cinv[NG];
__device__ float g_p[(size_t)NN * DD];
__device__ float g_q[(size_t)NN * DD];
__device__ float g_h1[(size_t)NN * DD];
__device__ float g_h2[(size_t)NN * DD];
__device__ float g_z[(size_t)NN * 4];
__device__ float g_Wcl[DD * 2];
__device__ float g_Wcr[DD * 2];
__device__ float g_cb[2];
__device__ float g_acc[NG * 2];

// ---------------- dtype detection (int32 vs int64) ----------------
__global__ void detect_kernel(const void* ei, const void* batch) {
    const long long* p = (const long long*)ei;
    bool e64 = true;
    #pragma unroll
    for (int i = 0; i < 16; i++) {
        long long v = p[(size_t)i * 99991];
        if (v < 0 || v >= NN) e64 = false;
    }
    g_ei64 = e64 ? 1 : 0;
    const long long* q = (const long long*)batch;  // sorted: sample near the end
    bool b64 = true;
    #pragma unroll
    for (int i = 0; i < 8; i++) {
        long long v = q[NN / 2 - 1 - i * 37];
        if (v < 0 || v >= NG) b64 = false;
    }
    g_b64 = b64 ? 1 : 0;
}

__device__ __forceinline__ int ld_ei(const void* p, long long i) {
    return g_ei64 ? (int)((const long long*)p)[i] : ((const int*)p)[i];
}
__device__ __forceinline__ int ld_b(const void* p, long long i) {
    return g_b64 ? (int)((const long long*)p)[i] : ((const int*)p)[i];
}

// ---------------- small init ----------------
__global__ void zero_small_kernel() {
    int i = blockIdx.x * blockDim.x + threadIdx.x;
    if (i < NN) g_degi[i] = 0;
    if (i < NG) g_cnti[i] = 0;
    if (i < NG * 2) g_acc[i] = 0.0f;
}

// ---------------- degree (random atomics) ----------------
__global__ void deg_kernel(const void* __restrict__ ei) {
    int e = blockIdx.x * blockDim.x + threadIdx.x;
    if (e >= EE) return;
    unsigned d = (unsigned)ld_ei(ei, (long long)EE + e);
    if (d >= NN) return;
    atomicAdd(&g_degi[d], 1);
}

// ---------------- batch histogram via shared memory ----------------
__global__ void __launch_bounds__(256) cnt_hist_kernel(const void* __restrict__ batch) {
    __shared__ int sh[NG];
    if (threadIdx.x < NG) sh[threadIdx.x] = 0;
    __syncthreads();
    int i = blockIdx.x * blockDim.x + threadIdx.x;
    if (i < NN) {
        unsigned g = (unsigned)ld_b(batch, i);
        if (g < NG) atomicAdd(&sh[g], 1);
    }
    __syncthreads();
    if (threadIdx.x < NG && sh[threadIdx.x] != 0) atomicAdd(&g_cnti[threadIdx.x], sh[threadIdx.x]);
}

__global__ void cinv_kernel() {
    int t = threadIdx.x;
    if (t < NG) g_cinv[t] = 1.0f / fmaxf((float)g_cnti[t], 1.0f);
}

// ---------------- exclusive scan over degrees (3 kernels) ----------------
__global__ void __launch_bounds__(256) scan1_kernel() {
    __shared__ int sdata[256];
    int t = threadIdx.x;
    int i = blockIdx.x * 256 + t;
    int v = (i < NN) ? g_degi[i] : 0;
    sdata[t] = v;
    __syncthreads();
    #pragma unroll
    for (int off = 1; off < 256; off <<= 1) {
        int x = (t >= off) ? sdata[t - off] : 0;
        __syncthreads();
        sdata[t] += x;
        __syncthreads();
    }
    int incl = sdata[t];
    if (i < NN) g_start[i] = incl - v;
    if (t == 255) g_bsum[blockIdx.x] = incl;
}

__global__ void __launch_bounds__(512) scan2_kernel(int nb) {
    __shared__ int sdata[512];
    int t = threadIdx.x;
    int v = (t < nb) ? g_bsum[t] : 0;
    sdata[t] = v;
    __syncthreads();
    #pragma unroll
    for (int off = 1; off < 512; off <<= 1) {
        int x = (t >= off) ? sdata[t - off] : 0;
        __syncthreads();
        sdata[t] += x;
        __syncthreads();
    }
    if (t < nb) g_bsum[t] = sdata[t] - v;   // exclusive
}

__global__ void __launch_bounds__(256) scan3_kernel() {
    int i = blockIdx.x * 256 + threadIdx.x;
    if (i >= NN) return;
    int s = g_start[i] + g_bsum[i >> 8];
    g_start[i] = s;
    g_cursor[i] = s;
    g_winv[i] = 1.0f / fmaxf((float)g_degi[i], 1.0f);
}

// ---------------- CSR placement ----------------
__global__ void __launch_bounds__(256) place_kernel(const void* __restrict__ ei) {
    int e = blockIdx.x * blockDim.x + threadIdx.x;
    if (e >= EE) return;
    unsigned s = (unsigned)ld_ei(ei, e);
    unsigned d = (unsigned)ld_ei(ei, (long long)EE + e);
    if (s >= NN || d >= NN) return;
    int pos = atomicAdd(&g_cursor[d], 1);
    g_csr[pos] = (int)s;
}

// ---------------- 3xTF32 tensor-core GEMM: Out = X(Nx128) @ W(128x128) ----------------
__device__ __forceinline__ void tf32_split(float x, float& hi, float& lo) {
    unsigned h;
    asm("cvt.rna.tf32.f32 %0, %1;" : "=r"(h) : "f"(x));
    float fh = __uint_as_float(h);
    float r = x - fh;
    unsigned l;
    asm("cvt.rna.tf32.f32 %0, %1;" : "=r"(l) : "f"(r));
    hi = fh;
    lo = __uint_as_float(l);
}

__device__ __forceinline__ void mma_tf32(float* d, const unsigned* a, const unsigned* b) {
    asm volatile(
        "mma.sync.aligned.m16n8k8.row.col.f32.tf32.tf32.f32 "
        "{%0,%1,%2,%3}, {%4,%5,%6,%7}, {%8,%9}, {%0,%1,%2,%3};"
        : "+f"(d[0]), "+f"(d[1]), "+f"(d[2]), "+f"(d[3])
        : "r"(a[0]), "r"(a[1]), "r"(a[2]), "r"(a[3]), "r"(b[0]), "r"(b[1]));
}

// Block: 128 rows x 128 cols; 128 threads = 4 warps (2x2 warp grid, warp tile 64x64).
// blockIdx.y: 0 -> Wl/P, 1 -> Wr/Q.
__global__ void __launch_bounds__(128) gemm3x_kernel(const float* __restrict__ X,
                                                     const float* __restrict__ Wl,
                                                     const float* __restrict__ Wr,
                                                     float* __restrict__ Pout,
                                                     float* __restrict__ Qout) {
    __shared__ float As_hi[16][136], As_lo[16][136];
    __shared__ float Ws_hi[16][136], Ws_lo[16][136];
    const float* W = blockIdx.y ? Wr : Wl;
    float* Out = blockIdx.y ? Qout : Pout;
    int row0 = blockIdx.x * 128;
    int tid = threadIdx.x;
    int warp = tid >> 5, lane = tid & 31;
    int g = lane >> 2, t = lane & 3;
    int wm = (warp >> 1) * 64;   // warp row base within tile
    int wn = (warp & 1) * 64;    // warp col base within tile

    float acc[4][8][4];
    #pragma unroll
    for (int a = 0; a < 4; a++)
        #pragma unroll
        for (int b = 0; b < 8; b++)
            #pragma unroll
            for (int c = 0; c < 4; c++) acc[a][b][c] = 0.0f;

    for (int ko = 0; ko < DD; ko += 16) {
        // -------- global loads --------
        float4 av[4], wv[4];
        #pragma unroll
        for (int i = 0; i < 4; i++) {
            int slot = tid + 128 * i;          // 0..511
            int m = slot >> 2;                 // 0..127
            int k4 = (slot & 3) * 4;           // {0,4,8,12}
            int r = row0 + m;
            av[i] = (r < NN) ? *(const float4*)(X + (size_t)r * DD + ko + k4)
                             : make_float4(0.f, 0.f, 0.f, 0.f);
        }
        #pragma unroll
        for (int i = 0; i < 4; i++) {
            int slot = tid + 128 * i;
            int k = slot >> 5;                 // 0..15
            int n = (slot & 31) * 4;           // 0..124
            wv[i] = *(const float4*)(W + (size_t)(ko + k) * DD + n);
        }
        __syncthreads();
        // -------- split + store to smem --------
        #pragma unroll
        for (int i = 0; i < 4; i++) {
            int slot = tid + 128 * i;
            int m = slot >> 2;
            int k4 = (slot & 3) * 4;
            float h, l;
            tf32_split(av[i].x, h, l); As_hi[k4 + 0][m] = h; As_lo[k4 + 0][m] = l;
            tf32_split(av[i].y, h, l); As_hi[k4 + 1][m] = h; As_lo[k4 + 1][m] = l;
            tf32_split(av[i].z, h, l); As_hi[k4 + 2][m] = h; As_lo[k4 + 2][m] = l;
            tf32_split(av[i].w, h, l); As_hi[k4 + 3][m] = h; As_lo[k4 + 3][m] = l;
        }
        #pragma unroll
        for (int i = 0; i < 4; i++) {
            int slot = tid + 128 * i;
            int k = slot >> 5;
            int n = (slot & 31) * 4;
            float4 h4, l4;
            tf32_split(wv[i].x, h4.x, l4.x);
            tf32_split(wv[i].y, h4.y, l4.y);
            tf32_split(wv[i].z, h4.z, l4.z);
            tf32_split(wv[i].w, h4.w, l4.w);
            *(float4*)&Ws_hi[k][n] = h4;
            *(float4*)&Ws_lo[k][n] = l4;
        }
        __syncthreads();
        // -------- compute: 2 k8 steps --------
        #pragma unroll
        for (int kk = 0; kk < 2; kk++) {
            int kb = kk * 8;
            unsigned ah[4][4], al[4][4];
            #pragma unroll
            for (int mt = 0; mt < 4; mt++) {
                int r = wm + mt * 16;
                ah[mt][0] = __float_as_uint(As_hi[kb + t][r + g]);
                ah[mt][1] = __float_as_uint(As_hi[kb + t][r + g + 8]);
                ah[mt][2] = __float_as_uint(As_hi[kb + t + 4][r + g]);
                ah[mt][3] = __float_as_uint(As_hi[kb + t + 4][r + g + 8]);
                al[mt][0] = __float_as_uint(As_lo[kb + t][r + g]);
                al[mt][1] = __float_as_uint(As_lo[kb + t][r + g + 8]);
                al[mt][2] = __float_as_uint(As_lo[kb + t + 4][r + g]);
                al[mt][3] = __float_as_uint(As_lo[kb + t + 4][r + g + 8]);
            }
            #pragma unroll
            for (int nt = 0; nt < 8; nt++) {
                int c = wn + nt * 8;
                unsigned bh[2], bl2[2];
                bh[0] = __float_as_uint(Ws_hi[kb + t][c + g]);
                bh[1] = __float_as_uint(Ws_hi[kb + t + 4][c + g]);
                bl2[0] = __float_as_uint(Ws_lo[kb + t][c + g]);
                bl2[1] = __float_as_uint(Ws_lo[kb + t + 4][c + g]);
                #pragma unroll
                for (int mt = 0; mt < 4; mt++) {
                    mma_tf32(acc[mt][nt], ah[mt], bh);
                    mma_tf32(acc[mt][nt], al[mt], bh);
                    mma_tf32(acc[mt][nt], ah[mt], bl2);
                }
            }
        }
    }
    // -------- epilogue --------
    #pragma unroll
    for (int mt = 0; mt < 4; mt++) {
        #pragma unroll
        for (int nt = 0; nt < 8; nt++) {
            int r = row0 + wm + mt * 16 + g;
            int c = wn + nt * 8 + 2 * t;
            if (r < NN) {
                float2 v = make_float2(acc[mt][nt][0], acc[mt][nt][1]);
                *(float2*)(Out + (size_t)r * DD + c) = v;
            }
            if (r + 8 < NN) {
                float2 v = make_float2(acc[mt][nt][2], acc[mt][nt][3]);
                *(float2*)(Out + (size_t)(r + 8) * DD + c) = v;
            }
        }
    }
}

// ---------------- CSR gather + epilogue: H = relu(winv * sum(P[nbr]) + Q + b) ----------------
__global__ void __launch_bounds__(256) gather_kernel(const float* __restrict__ P,
                                                     const float* __restrict__ Q,
                                                     const float* __restrict__ bias,
                                                     float* __restrict__ H) {
    int node = blockIdx.x * 8 + (threadIdx.x >> 5);
    int lane = threadIdx.x & 31;
    int s = g_start[node];
    int d = g_degi[node];
    float4 acc = make_float4(0.f, 0.f, 0.f, 0.f);
    for (int j = 0; j < d; j++) {
        int src = g_csr[s + j];
        float4 v = ((const float4*)(P + (size_t)src * DD))[lane];
        acc.x += v.x; acc.y += v.y; acc.z += v.z; acc.w += v.w;
    }
    float w = g_winv[node];
    float4 q = ((const float4*)(Q + (size_t)node * DD))[lane];
    float4 b = ((const float4*)bias)[lane];
    float4 o;
    o.x = fmaxf(acc.x * w + q.x + b.x, 0.0f);
    o.y = fmaxf(acc.y * w + q.y + b.y, 0.0f);
    o.z = fmaxf(acc.z * w + q.z + b.z, 0.0f);
    o.w = fmaxf(acc.w * w + q.w + b.w, 0.0f);
    ((float4*)(H + (size_t)node * DD))[lane] = o;
}

// ---------------- layer-3 fold ----------------
__global__ void foldW_kernel(const float* __restrict__ Wl3, const float* __restrict__ Wr3,
                             const float* __restrict__ bl3, const float* __restrict__ Wlin,
                             const float* __restrict__ blin) {
    int k = threadIdx.x;
    float a0 = 0.f, a1 = 0.f, b0 = 0.f, b1 = 0.f;
    for (int m = 0; m < DD; m++) {
        float wl = Wl3[k * DD + m], wr = Wr3[k * DD + m];
        float l0 = Wlin[m * 2 + 0], l1 = Wlin[m * 2 + 1];
        a0 += wl * l0; a1 += wl * l1;
        b0 += wr * l0; b1 += wr * l1;
    }
    g_Wcl[k * 2 + 0] = a0; g_Wcl[k * 2 + 1] = a1;
    g_Wcr[k * 2 + 0] = b0; g_Wcr[k * 2 + 1] = b1;
    if (k < 2) {
        float cv = blin[k];
        for (int m = 0; m < DD; m++) cv += bl3[m] * Wlin[m * 2 + k];
        g_cb[k] = cv;
    }
}

// ---------------- project h2 -> z (4 scalars/node) ----------------
__global__ void __launch_bounds__(256) proj3_kernel(const float* __restrict__ H2) {
    long long idx = (long long)blockIdx.x * blockDim.x + threadIdx.x;
    int node = (int)(idx >> 5);
    int lane = (int)(idx & 31);
    float4 h = ((const float4*)(H2 + (size_t)node * DD))[lane];
    float hv[4] = {h.x, h.y, h.z, h.w};
    float s0 = 0.f, s1 = 0.f, s2 = 0.f, s3 = 0.f;
    #pragma unroll
    for (int j = 0; j < 4; j++) {
        int k = lane * 4 + j;
        s0 += hv[j] * g_Wcl[k * 2 + 0];
        s1 += hv[j] * g_Wcl[k * 2 + 1];
        s2 += hv[j] * g_Wcr[k * 2 + 0];
        s3 += hv[j] * g_Wcr[k * 2 + 1];
    }
    #pragma unroll
    for (int o = 16; o > 0; o >>= 1) {
        s0 += __shfl_down_sync(0xFFFFFFFFu, s0, o);
        s1 += __shfl_down_sync(0xFFFFFFFFu, s1, o);
        s2 += __shfl_down_sync(0xFFFFFFFFu, s2, o);
        s3 += __shfl_down_sync(0xFFFFFFFFu, s3, o);
    }
    if (lane == 0) ((float4*)g_z)[node] = make_float4(s0, s1, s2, s3);
}

// ---------------- layer-3 pooled reduction (CSR, thread per node) ----------------
__global__ void __launch_bounds__(256) pool3_kernel(const void* __restrict__ batch) {
    __shared__ float sh[NG * 2];
    for (int i = threadIdx.x; i < NG * 2; i += blockDim.x) sh[i] = 0.0f;
    __syncthreads();
    int n = blockIdx.x * 256 + threadIdx.x;
    if (n < NN) {
        int s = g_start[n], d = g_degi[n];
        float s0 = 0.f, s1 = 0.f;
        for (int j = 0; j < d; j++) {
            int src = g_csr[s + j];
            float2 zl = *(const float2*)(g_z + (size_t)src * 4);
            s0 += zl.x; s1 += zl.y;
        }
        float w = g_winv[n];
        unsigned gg = (unsigned)ld_b(batch, n);
        if (gg < NG) {
            float ci = g_cinv[gg];
            float2 zr = *(const float2*)(g_z + (size_t)n * 4 + 2);
            atomicAdd(&sh[gg * 2 + 0], ci * (w * s0 + zr.x));
            atomicAdd(&sh[gg * 2 + 1], ci * (w * s1 + zr.y));
        }
    }
    __syncthreads();
    for (int i = threadIdx.x; i < NG * 2; i += blockDim.x)
        if (sh[i] != 0.0f) atomicAdd(&g_acc[i], sh[i]);
}

__global__ void finalize_kernel(float* __restrict__ out) {
    int t = threadIdx.x;
    if (t < NG * 2) out[t] = g_acc[t] + g_cb[t & 1];
}

// ---------------- host launcher ----------------
extern "C" void kernel_launch(void* const* d_in, const int* in_sizes, int n_in,
                              void* d_out, int out_size) {
    const float* x = (const float*)d_in[0];
    const void* ei = d_in[1];
    const void* batch = d_in[2];
    const float* Wl1 = (const float*)d_in[3];
    const float* bl1 = (const float*)d_in[4];
    const float* Wr1 = (const float*)d_in[5];
    const float* Wl2 = (const float*)d_in[6];
    const float* bl2 = (const float*)d_in[7];
    const float* Wr2 = (const float*)d_in[8];
    const float* Wl3 = (const float*)d_in[9];
    const float* bl3 = (const float*)d_in[10];
    const float* Wr3 = (const float*)d_in[11];
    const float* Wlin = (const float*)d_in[12];
    const float* blin = (const float*)d_in[13];
    float* out = (float*)d_out;

    // __device__ symbols are not host pointers: resolve real addresses.
    float *pp = nullptr, *qp = nullptr, *h1p = nullptr, *h2p = nullptr;
    cudaGetSymbolAddress((void**)&pp, g_p);
    cudaGetSymbolAddress((void**)&qp, g_q);
    cudaGetSymbolAddress((void**)&h1p, g_h1);
    cudaGetSymbolAddress((void**)&h2p, g_h2);

    const int nb = (NN + 255) / 256;   // 391

    detect_kernel<<<1, 1>>>(ei, batch);
    zero_small_kernel<<<nb, 256>>>();
    deg_kernel<<<(EE + 255) / 256, 256>>>(ei);
    cnt_hist_kernel<<<nb, 256>>>(batch);
    cinv_kernel<<<1, 64>>>();
    scan1_kernel<<<nb, 256>>>();
    scan2_kernel<<<1, 512>>>(nb);
    scan3_kernel<<<nb, 256>>>();
    place_kernel<<<(EE + 255) / 256, 256>>>(ei);

    dim3 gg((NN + 127) / 128, 2);
    // layer 1
    gemm3x_kernel<<<gg, 128>>>(x, Wl1, Wr1, pp, qp);
    gather_kernel<<<NN / 8, 256>>>(pp, qp, bl1, h1p);
    // layer 2
    gemm3x_kernel<<<gg, 128>>>(h1p, Wl2, Wr2, pp, qp);
    gather_kernel<<<NN / 8, 256>>>(pp, qp, bl2, h2p);
    // layer 3 folded through linear head
    foldW_kernel<<<1, 128>>>(Wl3, Wr3, bl3, Wlin, blin);
    proj3_kernel<<<NN * 32 / 256, 256>>>(h2p);
    pool3_kernel<<<nb, 256>>>(batch);
    finalize_kernel<<<1, 128>>>(out);
}

// round 5
// speedup vs baseline: 2.3981x; 1.3152x over previous
#include <cuda_runtime.h>
#include <cstdint>

#define NN 100000
#define EE 1600000
#define DD 128
#define NG 64

// ---------------- scratch (static device globals; no allocation) ----------------
__device__ int      g_ei64, g_b64;
__device__ int      g_degi[NN];
__device__ int      g_start[NN];
__device__ int      g_cursor[NN];
__device__ int      g_bsum[512];
__device__ int      g_cnti[NG];
__device__ int      g_csr[EE];
__device__ float    g_winv[NN];
__device__ float    g_cinv[NG];
__device__ float    g_p[(size_t)NN * DD];
__device__ float    g_q[(size_t)NN * DD];
__device__ float    g_h1[(size_t)NN * DD];
__device__ float    g_z[(size_t)NN * 4];
__device__ unsigned g_wsp[4][2][64][DD];   // pre-split weights: [matrix][plane][k/2][n] bf16x2
__device__ float    g_Wcl[DD * 2];
__device__ float    g_Wcr[DD * 2];
__device__ float    g_cb[2];
__device__ float    g_acc[NG * 2];

// ---------------- helpers ----------------
__device__ __forceinline__ unsigned pack_bf2(float lo, float hi) {
    unsigned r;
    asm("cvt.rn.bf16x2.f32 %0, %1, %2;" : "=r"(r) : "f"(hi), "f"(lo));
    return r;
}
// split (x0,x1) -> plane0 (hi bf16 pair), plane1 (residual bf16 pair); residual <= 2^-17 rel
__device__ __forceinline__ void split2(float x0, float x1, unsigned& p0, unsigned& p1) {
    p0 = pack_bf2(x0, x1);
    float h0 = __uint_as_float(p0 << 16);
    float h1 = __uint_as_float(p0 & 0xFFFF0000u);
    p1 = pack_bf2(x0 - h0, x1 - h1);
}

__device__ __forceinline__ void mma_bf16(float* d, const unsigned* a, const unsigned* b) {
    asm volatile(
        "mma.sync.aligned.m16n8k16.row.col.f32.bf16.bf16.f32 "
        "{%0,%1,%2,%3}, {%4,%5,%6,%7}, {%8,%9}, {%0,%1,%2,%3};"
        : "+f"(d[0]), "+f"(d[1]), "+f"(d[2]), "+f"(d[3])
        : "r"(a[0]), "r"(a[1]), "r"(a[2]), "r"(a[3]), "r"(b[0]), "r"(b[1]));
}

// ---------------- dtype detection (int32 vs int64) ----------------
__global__ void detect_kernel(const void* ei, const void* batch) {
    const long long* p = (const long long*)ei;
    bool e64 = true;
    #pragma unroll
    for (int i = 0; i < 16; i++) {
        long long v = p[(size_t)i * 99991];
        if (v < 0 || v >= NN) e64 = false;
    }
    g_ei64 = e64 ? 1 : 0;
    const long long* q = (const long long*)batch;  // sorted: sample near the end
    bool b64 = true;
    #pragma unroll
    for (int i = 0; i < 8; i++) {
        long long v = q[NN / 2 - 1 - i * 37];
        if (v < 0 || v >= NG) b64 = false;
    }
    g_b64 = b64 ? 1 : 0;
}

__device__ __forceinline__ int ld_ei(const void* p, long long i) {
    return g_ei64 ? (int)((const long long*)p)[i] : ((const int*)p)[i];
}
__device__ __forceinline__ int ld_b(const void* p, long long i) {
    return g_b64 ? (int)((const long long*)p)[i] : ((const int*)p)[i];
}

// ---------------- small init ----------------
__global__ void zero_small_kernel() {
    int i = blockIdx.x * blockDim.x + threadIdx.x;
    if (i < NN) g_degi[i] = 0;
    if (i < NG) g_cnti[i] = 0;
    if (i < NG * 2) g_acc[i] = 0.0f;
}

// ---------------- pre-split W matrices into bf16 hi/lo planes ----------------
__global__ void __launch_bounds__(256) presplit_kernel(const float* __restrict__ Wl1,
                                                       const float* __restrict__ Wr1,
                                                       const float* __restrict__ Wl2,
                                                       const float* __restrict__ Wr2) {
    int idx = blockIdx.x * 256 + threadIdx.x;   // 0..32767
    int mat = idx >> 13;
    int rem = idx & 8191;
    int k2 = rem >> 7;
    int n = rem & 127;
    const float* W = (mat == 0) ? Wl1 : (mat == 1) ? Wr1 : (mat == 2) ? Wl2 : Wr2;
    float w0 = W[(2 * k2) * DD + n];
    float w1 = W[(2 * k2 + 1) * DD + n];
    unsigned p0, p1;
    split2(w0, w1, p0, p1);                      // lo half = even k
    g_wsp[mat][0][k2][n] = p0;
    g_wsp[mat][1][k2][n] = p1;
}

// ---------------- bf16x3 GEMM: P = X@W[matL], Q = X@W[matR] in one block pass ----------------
// 128 threads (4 warps, 2x2 warpgrid, warp tile 64x64). Full A tile split cached in smem.
extern __shared__ unsigned sm_dyn[];
#define GEMM_SMEM ((2 * 64 * 136 + 2 * 8 * 136) * 4)

__global__ void __launch_bounds__(128) gemm_bf16x3_kernel(const float* __restrict__ X,
                                                          int matL, int matR,
                                                          float* __restrict__ Pout,
                                                          float* __restrict__ Qout) {
    unsigned* As0 = sm_dyn;                    // [64][136]
    unsigned* As1 = sm_dyn + 64 * 136;
    unsigned* Bs0 = sm_dyn + 2 * 64 * 136;     // [8][136]
    unsigned* Bs1 = Bs0 + 8 * 136;

    int tid = threadIdx.x;
    int warp = tid >> 5, lane = tid & 31;
    int g = lane >> 2, t = lane & 3;
    int wm = (warp >> 1) * 64, wn = (warp & 1) * 64;
    int row0 = blockIdx.x * 128;

    // ---- load & split the full 128x128 A tile ----
    #pragma unroll
    for (int ko = 0; ko < DD; ko += 16) {
        #pragma unroll
        for (int i = 0; i < 4; i++) {
            int slot = tid + 128 * i;
            int m = slot >> 2;
            int k4 = (slot & 3) * 4;
            int r = row0 + m;
            float4 av = (r < NN) ? *(const float4*)(X + (size_t)r * DD + ko + k4)
                                 : make_float4(0.f, 0.f, 0.f, 0.f);
            unsigned p0, p1, q0, q1;
            split2(av.x, av.y, p0, p1);
            split2(av.z, av.w, q0, q1);
            int k2 = (ko + k4) >> 1;
            As0[k2 * 136 + m] = p0;  As0[(k2 + 1) * 136 + m] = q0;
            As1[k2 * 136 + m] = p1;  As1[(k2 + 1) * 136 + m] = q1;
        }
    }
    __syncthreads();

    #pragma unroll
    for (int phase = 0; phase < 2; phase++) {
        const unsigned* Wsp = &g_wsp[phase ? matR : matL][0][0][0];  // [2][64][128]
        float* Out = phase ? Qout : Pout;
        float acc[4][8][4];
        #pragma unroll
        for (int a = 0; a < 4; a++)
            #pragma unroll
            for (int b = 0; b < 8; b++)
                #pragma unroll
                for (int c = 0; c < 4; c++) acc[a][b][c] = 0.0f;

        for (int ko2 = 0; ko2 < 64; ko2 += 8) {   // 8 k16-chunks
            __syncthreads();  // previous Bs fully consumed
            #pragma unroll
            for (int i = 0; i < 4; i++) {
                int slot = tid + 128 * i;          // uint4 slots, 512 total
                int p = slot >> 8;
                int rem = slot & 255;
                int k2l = rem >> 5;
                int n4 = (rem & 31) * 4;
                uint4 v = *(const uint4*)(Wsp + ((size_t)p * 64 + ko2 + k2l) * DD + n4);
                *(uint4*)((p ? Bs1 : Bs0) + k2l * 136 + n4) = v;
            }
            __syncthreads();

            unsigned a0f[4][4], a1f[4][4];
            #pragma unroll
            for (int mt = 0; mt < 4; mt++) {
                int m = wm + mt * 16 + g;
                a0f[mt][0] = As0[(ko2 + t) * 136 + m];
                a0f[mt][1] = As0[(ko2 + t) * 136 + m + 8];
                a0f[mt][2] = As0[(ko2 + t + 4) * 136 + m];
                a0f[mt][3] = As0[(ko2 + t + 4) * 136 + m + 8];
                a1f[mt][0] = As1[(ko2 + t) * 136 + m];
                a1f[mt][1] = As1[(ko2 + t) * 136 + m + 8];
                a1f[mt][2] = As1[(ko2 + t + 4) * 136 + m];
                a1f[mt][3] = As1[(ko2 + t + 4) * 136 + m + 8];
            }
            #pragma unroll
            for (int nt = 0; nt < 8; nt++) {
                int n = wn + nt * 8 + g;
                unsigned b0[2], b1[2];
                b0[0] = Bs0[t * 136 + n];
                b0[1] = Bs0[(t + 4) * 136 + n];
                b1[0] = Bs1[t * 136 + n];
                b1[1] = Bs1[(t + 4) * 136 + n];
                #pragma unroll
                for (int mt = 0; mt < 4; mt++) {
                    mma_bf16(acc[mt][nt], a0f[mt], b0);
                    mma_bf16(acc[mt][nt], a0f[mt], b1);
                    mma_bf16(acc[mt][nt], a1f[mt], b0);
                }
            }
        }
        // epilogue
        #pragma unroll
        for (int mt = 0; mt < 4; mt++) {
            #pragma unroll
            for (int nt = 0; nt < 8; nt++) {
                int r = row0 + wm + mt * 16 + g;
                int c = wn + nt * 8 + 2 * t;
                if (r < NN)
                    *(float2*)(Out + (size_t)r * DD + c) = make_float2(acc[mt][nt][0], acc[mt][nt][1]);
                if (r + 8 < NN)
                    *(float2*)(Out + (size_t)(r + 8) * DD + c) = make_float2(acc[mt][nt][2], acc[mt][nt][3]);
            }
        }
    }
}

// ---------------- degree / counts / scan / place ----------------
__global__ void deg_kernel(const void* __restrict__ ei) {
    int e = blockIdx.x * blockDim.x + threadIdx.x;
    if (e >= EE) return;
    unsigned d = (unsigned)ld_ei(ei, (long long)EE + e);
    if (d >= NN) return;
    atomicAdd(&g_degi[d], 1);
}

__global__ void __launch_bounds__(256) cnt_hist_kernel(const void* __restrict__ batch) {
    __shared__ int sh[NG];
    if (threadIdx.x < NG) sh[threadIdx.x] = 0;
    __syncthreads();
    int i = blockIdx.x * blockDim.x + threadIdx.x;
    if (i < NN) {
        unsigned g = (unsigned)ld_b(batch, i);
        if (g < NG) atomicAdd(&sh[g], 1);
    }
    __syncthreads();
    if (threadIdx.x < NG && sh[threadIdx.x] != 0) atomicAdd(&g_cnti[threadIdx.x], sh[threadIdx.x]);
}

__global__ void __launch_bounds__(256) scan1_kernel() {
    __shared__ int sdata[256];
    int t = threadIdx.x;
    int i = blockIdx.x * 256 + t;
    int v = (i < NN) ? g_degi[i] : 0;
    sdata[t] = v;
    __syncthreads();
    #pragma unroll
    for (int off = 1; off < 256; off <<= 1) {
        int x = (t >= off) ? sdata[t - off] : 0;
        __syncthreads();
        sdata[t] += x;
        __syncthreads();
    }
    int incl = sdata[t];
    if (i < NN) g_start[i] = incl - v;
    if (t == 255) g_bsum[blockIdx.x] = incl;
}

__global__ void __launch_bounds__(512) scan2_kernel(int nb) {
    __shared__ int sdata[512];
    int t = threadIdx.x;
    int v = (t < nb) ? g_bsum[t] : 0;
    sdata[t] = v;
    __syncthreads();
    #pragma unroll
    for (int off = 1; off < 512; off <<= 1) {
        int x = (t >= off) ? sdata[t - off] : 0;
        __syncthreads();
        sdata[t] += x;
        __syncthreads();
    }
    if (t < nb) g_bsum[t] = sdata[t] - v;   // exclusive
    if (t < NG) g_cinv[t] = 1.0f / fmaxf((float)g_cnti[t], 1.0f);
}

__global__ void __launch_bounds__(256) scan3_kernel() {
    int i = blockIdx.x * 256 + threadIdx.x;
    if (i >= NN) return;
    int s = g_start[i] + g_bsum[i >> 8];
    g_start[i] = s;
    g_cursor[i] = s;
    g_winv[i] = 1.0f / fmaxf((float)g_degi[i], 1.0f);
}

__global__ void __launch_bounds__(256) place_kernel(const void* __restrict__ ei) {
    int e = blockIdx.x * blockDim.x + threadIdx.x;
    if (e >= EE) return;
    unsigned s = (unsigned)ld_ei(ei, e);
    unsigned d = (unsigned)ld_ei(ei, (long long)EE + e);
    if (s >= NN || d >= NN) return;
    int pos = atomicAdd(&g_cursor[d], 1);
    g_csr[pos] = (int)s;
}

// ---------------- CSR gather + epilogue: H = relu(winv * sum(P[nbr]) + Q + b) ----------------
__global__ void __launch_bounds__(256) gather_kernel(const float* __restrict__ P,
                                                     const float* __restrict__ Q,
                                                     const float* __restrict__ bias,
                                                     float* __restrict__ H) {
    int node = blockIdx.x * 8 + (threadIdx.x >> 5);
    int lane = threadIdx.x & 31;
    int s = g_start[node];
    int d = g_degi[node];
    float4 acc = make_float4(0.f, 0.f, 0.f, 0.f);
    for (int j = 0; j < d; j++) {
        int src = g_csr[s + j];
        float4 v = ((const float4*)(P + (size_t)src * DD))[lane];
        acc.x += v.x; acc.y += v.y; acc.z += v.z; acc.w += v.w;
    }
    float w = g_winv[node];
    float4 q = ((const float4*)(Q + (size_t)node * DD))[lane];
    float4 b = ((const float4*)bias)[lane];
    float4 o;
    o.x = fmaxf(acc.x * w + q.x + b.x, 0.0f);
    o.y = fmaxf(acc.y * w + q.y + b.y, 0.0f);
    o.z = fmaxf(acc.z * w + q.z + b.z, 0.0f);
    o.w = fmaxf(acc.w * w + q.w + b.w, 0.0f);
    ((float4*)(H + (size_t)node * DD))[lane] = o;
}

// ---------------- layer-2 gather fused with layer-3 projection -> z (no h2 roundtrip) ----------------
__global__ void __launch_bounds__(256) gather2z_kernel(const float* __restrict__ P,
                                                       const float* __restrict__ Q,
                                                       const float* __restrict__ bias) {
    int node = blockIdx.x * 8 + (threadIdx.x >> 5);
    int lane = threadIdx.x & 31;
    int s = g_start[node];
    int d = g_degi[node];
    float4 acc = make_float4(0.f, 0.f, 0.f, 0.f);
    for (int j = 0; j < d; j++) {
        int src = g_csr[s + j];
        float4 v = ((const float4*)(P + (size_t)src * DD))[lane];
        acc.x += v.x; acc.y += v.y; acc.z += v.z; acc.w += v.w;
    }
    float w = g_winv[node];
    float4 q = ((const float4*)(Q + (size_t)node * DD))[lane];
    float4 b = ((const float4*)bias)[lane];
    float hv[4];
    hv[0] = fmaxf(acc.x * w + q.x + b.x, 0.0f);
    hv[1] = fmaxf(acc.y * w + q.y + b.y, 0.0f);
    hv[2] = fmaxf(acc.z * w + q.z + b.z, 0.0f);
    hv[3] = fmaxf(acc.w * w + q.w + b.w, 0.0f);
    float s0 = 0.f, s1 = 0.f, s2 = 0.f, s3 = 0.f;
    #pragma unroll
    for (int j = 0; j < 4; j++) {
        int k = lane * 4 + j;
        s0 += hv[j] * g_Wcl[k * 2 + 0];
        s1 += hv[j] * g_Wcl[k * 2 + 1];
        s2 += hv[j] * g_Wcr[k * 2 + 0];
        s3 += hv[j] * g_Wcr[k * 2 + 1];
    }
    #pragma unroll
    for (int o = 16; o > 0; o >>= 1) {
        s0 += __shfl_down_sync(0xFFFFFFFFu, s0, o);
        s1 += __shfl_down_sync(0xFFFFFFFFu, s1, o);
        s2 += __shfl_down_sync(0xFFFFFFFFu, s2, o);
        s3 += __shfl_down_sync(0xFFFFFFFFu, s3, o);
    }
    if (lane == 0) ((float4*)g_z)[node] = make_float4(s0, s1, s2, s3);
}

// ---------------- layer-3 fold ----------------
__global__ void foldW_kernel(const float* __restrict__ Wl3, const float* __restrict__ Wr3,
                             const float* __restrict__ bl3, const float* __restrict__ Wlin,
                             const float* __restrict__ blin) {
    int k = threadIdx.x;
    float a0 = 0.f, a1 = 0.f, b0 = 0.f, b1 = 0.f;
    for (int m = 0; m < DD; m++) {
        float wl = Wl3[k * DD + m], wr = Wr3[k * DD + m];
        float l0 = Wlin[m * 2 + 0], l1 = Wlin[m * 2 + 1];
        a0 += wl * l0; a1 += wl * l1;
        b0 += wr * l0; b1 += wr * l1;
    }
    g_Wcl[k * 2 + 0] = a0; g_Wcl[k * 2 + 1] = a1;
    g_Wcr[k * 2 + 0] = b0; g_Wcr[k * 2 + 1] = b1;
    if (k < 2) {
        float cv = blin[k];
        for (int m = 0; m < DD; m++) cv += bl3[m] * Wlin[m * 2 + k];
        g_cb[k] = cv;
    }
}

// ---------------- layer-3 pooled reduction ----------------
__global__ void __launch_bounds__(256) pool3_kernel(const void* __restrict__ batch) {
    __shared__ float sh[NG * 2];
    for (int i = threadIdx.x; i < NG * 2; i += blockDim.x) sh[i] = 0.0f;
    __syncthreads();
    int n = blockIdx.x * 256 + threadIdx.x;
    if (n < NN) {
        int s = g_start[n], d = g_degi[n];
        float s0 = 0.f, s1 = 0.f;
        for (int j = 0; j < d; j++) {
            int src = g_csr[s + j];
            float2 zl = *(const float2*)(g_z + (size_t)src * 4);
            s0 += zl.x; s1 += zl.y;
        }
        float w = g_winv[n];
        unsigned gg = (unsigned)ld_b(batch, n);
        if (gg < NG) {
            float ci = g_cinv[gg];
            float2 zr = *(const float2*)(g_z + (size_t)n * 4 + 2);
            atomicAdd(&sh[gg * 2 + 0], ci * (w * s0 + zr.x));
            atomicAdd(&sh[gg * 2 + 1], ci * (w * s1 + zr.y));
        }
    }
    __syncthreads();
    for (int i = threadIdx.x; i < NG * 2; i += blockDim.x)
        if (sh[i] != 0.0f) atomicAdd(&g_acc[i], sh[i]);
}

__global__ void finalize_kernel(float* __restrict__ out) {
    int t = threadIdx.x;
    if (t < NG * 2) out[t] = g_acc[t] + g_cb[t & 1];
}

// ---------------- host launcher ----------------
extern "C" void kernel_launch(void* const* d_in, const int* in_sizes, int n_in,
                              void* d_out, int out_size) {
    const float* x = (const float*)d_in[0];
    const void* ei = d_in[1];
    const void* batch = d_in[2];
    const float* Wl1 = (const float*)d_in[3];
    const float* bl1 = (const float*)d_in[4];
    const float* Wr1 = (const float*)d_in[5];
    const float* Wl2 = (const float*)d_in[6];
    const float* bl2 = (const float*)d_in[7];
    const float* Wr2 = (const float*)d_in[8];
    const float* Wl3 = (const float*)d_in[9];
    const float* bl3 = (const float*)d_in[10];
    const float* Wr3 = (const float*)d_in[11];
    const float* Wlin = (const float*)d_in[12];
    const float* blin = (const float*)d_in[13];
    float* out = (float*)d_out;

    // __device__ symbols are not host pointers: resolve real addresses.
    float *pp = nullptr, *qp = nullptr, *h1p = nullptr;
    cudaGetSymbolAddress((void**)&pp, g_p);
    cudaGetSymbolAddress((void**)&qp, g_q);
    cudaGetSymbolAddress((void**)&h1p, g_h1);

    cudaFuncSetAttribute(gemm_bf16x3_kernel,
                         cudaFuncAttributeMaxDynamicSharedMemorySize, GEMM_SMEM);

    const int nb = (NN + 255) / 256;        // 391
    const int gemm_blocks = (NN + 127) / 128;  // 782

    detect_kernel<<<1, 1>>>(ei, batch);
    zero_small_kernel<<<nb, 256>>>();
    presplit_kernel<<<128, 256>>>(Wl1, Wr1, Wl2, Wr2);
    gemm_bf16x3_kernel<<<gemm_blocks, 128, GEMM_SMEM>>>(x, 0, 1, pp, qp);   // <- profile slot
    deg_kernel<<<(EE + 255) / 256, 256>>>(ei);
    cnt_hist_kernel<<<nb, 256>>>(batch);
    scan1_kernel<<<nb, 256>>>();
    scan2_kernel<<<1, 512>>>(nb);
    scan3_kernel<<<nb, 256>>>();
    place_kernel<<<(EE + 255) / 256, 256>>>(ei);

    gather_kernel<<<NN / 8, 256>>>(pp, qp, bl1, h1p);
    gemm_bf16x3_kernel<<<gemm_blocks, 128, GEMM_SMEM>>>(h1p, 2, 3, pp, qp);
    foldW_kernel<<<1, 128>>>(Wl3, Wr3, bl3, Wlin, blin);
    gather2z_kernel<<<NN / 8, 256>>>(pp, qp, bl2);
    pool3_kernel<<<nb, 256>>>(batch);
    finalize_kernel<<<1, 128>>>(out);
}